// round 7
// baseline (speedup 1.0000x reference)
#include <cuda_runtime.h>
#include <math.h>

#define PI_D 3.14159265358979323846

typedef unsigned long long u64t;

// ---------------- complex / packed helpers ----------------
__device__ __forceinline__ float2 cmul(float2 a, float2 b){
    return make_float2(a.x*b.x - a.y*b.y, a.x*b.y + a.y*b.x);
}
__device__ __forceinline__ void cfma(float2 &acc, float2 a, float2 b){
    acc.x = fmaf(a.x, b.x, fmaf(-a.y, b.y, acc.x));
    acc.y = fmaf(a.x, b.y, fmaf( a.y, b.x, acc.y));
}
__device__ __forceinline__ u64t pk2(float lo, float hi){
    u64t r; asm("mov.b64 %0, {%1, %2};" : "=l"(r) : "f"(lo), "f"(hi)); return r;
}
__device__ __forceinline__ u64t ffma2(u64t a, u64t b, u64t c){
    u64t d; asm("fma.rn.f32x2 %0, %1, %2, %3;" : "=l"(d) : "l"(a), "l"(b), "l"(c)); return d;
}
__device__ __forceinline__ float2 upk(u64t v){
    float lo, hi; asm("mov.b64 {%0, %1}, %2;" : "=f"(lo), "=f"(hi) : "l"(v));
    return make_float2(lo, hi);
}

// ---------------- device-global scratch & constant tables ----------------
__device__ double g_lf[48];
__device__ double g_w30d[60];
__device__ double g_w10d[20];
__device__ double g_w6d[12];
__device__ float  g_w2n[12];

__device__ float2 g_T60[19*60];
__device__ float2 g_iE20[19*20];
__device__ float2 g_fE20[11*20];
__device__ float2 g_iE12[11*12];

__device__ float  g_wd_s2[10*60*19];
__device__ float2 g_Y1[10*24*19];
__device__ float  g_d1w[10*20*361];
__device__ float  g_d12w[6*20*121];
__device__ float2 g_D2[6*144*121];
__device__ float  g_d2w[6*12*121];

__device__ float2 g_X[10*128*19];
__device__ float2 g_Psi1[10*20*19];
__device__ float4 g_Psi2d[6*20*40*121];   // dual form (p.x, p.y, -p.y, p.x)
__device__ float2 g_Fx[6*128*20*121];
__device__ float2 g_Foh[6*128*40*66];     // Fo half-spectrum: n >= 0 (66 of 121)
__device__ float  g_feat[128*40];

// ---------------- Wigner-d (explicit formula, FP64) ----------------
__device__ double wdfun(int l, int m, int n, double beta){
    if (m > l || m < -l || n > l || n < -l) return 0.0;
    double cb = cos(0.5*beta), sb = sin(0.5*beta);
    double lcb = log(cb), lsb = log(sb);
    double pref = 0.5*(g_lf[l+m] + g_lf[l-m] + g_lf[l+n] + g_lf[l-n]);
    int s0 = max(0, n-m), s1 = min(l+n, l-m);
    double acc = 0.0;
    for (int s = s0; s <= s1; s++){
        double c = pref - (g_lf[l+n-s] + g_lf[s] + g_lf[m-n+s] + g_lf[l-m-s]);
        double e = exp(c + (double)(2*l + n - m - 2*s)*lcb + (double)(m - n + 2*s)*lsb);
        acc += ((m - n + s) & 1) ? -e : e;
    }
    return acc;
}

// ---------------- launch 1: init ----------------
__global__ void k_init_misc(){
    int t = threadIdx.x;
    if (t < 48) g_lf[t] = lgamma((double)t + 1.0);
    if (t < 60){
        double beta = PI_D*(2*t+1)/120.0; double s = 0;
        for (int j = 0; j < 30; j++) s += sin((2*j+1)*beta)/(2*j+1);
        g_w30d[t] = (2.0/30.0)*sin(beta)*s;
    }
    if (t < 20){
        double beta = PI_D*(2*t+1)/40.0; double s = 0;
        for (int j = 0; j < 10; j++) s += sin((2*j+1)*beta)/(2*j+1);
        g_w10d[t] = (2.0/10.0)*sin(beta)*s;
    }
    if (t < 12){
        double beta = PI_D*(2*t+1)/24.0; double s = 0;
        for (int j = 0; j < 6; j++) s += sin((2*j+1)*beta)/(2*j+1);
        g_w6d[t] = (2.0/6.0)*sin(beta)*s;
    }
    __syncthreads();
    if (t == 0){
        double s = 0;
        for (int i = 0; i < 12; i++) s += g_w6d[i];
        for (int i = 0; i < 12; i++) g_w2n[i] = (float)(g_w6d[i]/s);
    }
    for (int idx = t; idx < 19*60; idx += blockDim.x){
        int mi = idx/60, a = idx%60; int m = mi - 9;
        double sn, cs; sincospi(-(double)(m*a)/30.0, &sn, &cs);
        g_T60[idx] = make_float2((float)cs, (float)sn);
    }
    for (int idx = t; idx < 19*20; idx += blockDim.x){
        int mi = idx/20, a = idx%20; int m = mi - 9;
        double sn, cs; sincospi((double)(m*a)/10.0, &sn, &cs);
        g_iE20[idx] = make_float2((float)cs, (float)sn);
    }
    for (int idx = t; idx < 11*20; idx += blockDim.x){
        int mi = idx/20, a = idx%20; int m = mi - 5;
        double sn, cs; sincospi(-(double)(m*a)/10.0, &sn, &cs);
        g_fE20[idx] = make_float2((float)cs, (float)sn);
    }
    for (int idx = t; idx < 11*12; idx += blockDim.x){
        int mi = idx/12, a = idx%12; int m = mi - 5;
        double sn, cs; sincospi((double)(m*a)/6.0, &sn, &cs);
        g_iE12[idx] = make_float2((float)cs, (float)sn);
    }
}

// ---------------- launch 2: all Wigner tables ----------------
#define N_WDS2 (10*60*19)
#define N_Y1   (10*24*19)
#define N_D1W  (10*20*361)
#define N_D12W (6*20*121)
#define N_D2   (6*144*121)
#define N_D2W  (6*12*121)
#define N_TABS (N_WDS2+N_Y1+N_D1W+N_D12W+N_D2+N_D2W)

__global__ void k_tabs(){
    int idx = blockIdx.x*blockDim.x + threadIdx.x;
    if (idx < N_WDS2){
        int l = idx/(60*19); int r = idx%(60*19); int k = r/19; int mi = r%19;
        double beta = PI_D*(2*k+1)/120.0;
        g_wd_s2[idx] = (float)(g_w30d[k]*wdfun(l, mi-9, 0, beta));
        return;
    }
    idx -= N_WDS2;
    if (idx < N_Y1){
        int l = idx/456; int r = idx%456; int gp = r/19; int mi = r%19;
        int ib = gp/8, ia = gp%8; int m = mi - 9;
        double beta = (ib+1)*PI_D/24.0;
        double d = wdfun(l, m, 0, beta);
        double sn, cs; sincospi(-(double)(m*ia)/4.0, &sn, &cs);
        g_Y1[idx] = make_float2((float)(d*cs), (float)(d*sn));
        return;
    }
    idx -= N_Y1;
    if (idx < N_D1W){
        int l = idx/(20*361); int r = idx%(20*361); int b = r/361; int mn = r%361;
        int m = mn/19 - 9, n = mn%19 - 9;
        double beta = PI_D*(2*b+1)/40.0;
        g_d1w[idx] = (float)(wdfun(l, m, n, beta)*(double)(2*l+1));
        return;
    }
    idx -= N_D1W;
    if (idx < N_D12W){
        int l = idx/(20*121); int r = idx%(20*121); int b = r/121; int mn = r%121;
        int m = mn/11 - 5, n = mn%11 - 5;
        double beta = PI_D*(2*b+1)/40.0;
        g_d12w[idx] = (float)(wdfun(l, m, n, beta)*g_w10d[b]);
        return;
    }
    idx -= N_D12W;
    if (idx < N_D2){
        int l = idx/(144*121); int r = idx%(144*121); int gp = r/121; int mn = r%121;
        int m = mn/11 - 5, n = mn%11 - 5;
        int ib = gp/48, ia = (gp/6)%8, ig = gp%6;
        double beta = (ib+1)*PI_D/24.0;
        double d = wdfun(l, m, n, beta);
        double ph = -((double)(m*ia)/4.0 + (double)(n*ig)/3.0);
        double sn, cs; sincospi(ph, &sn, &cs);
        g_D2[idx] = make_float2((float)(d*cs), (float)(d*sn));
        return;
    }
    idx -= N_D2;
    if (idx < N_D2W){
        int l = idx/(12*121); int r = idx%(12*121); int b = r/121; int mn = r%121;
        int m = mn/11 - 5, n = mn%11 - 5;
        double beta = PI_D*(2*b+1)/24.0;
        g_d2w[idx] = (float)(wdfun(l, m, n, beta)*(double)(2*l+1));
        return;
    }
}

// ---------------- launch 3 (kAB): kA (blocks 0-127) + kB (blocks 128-137) ----------------
__global__ void kAB(const float* __restrict__ x, const float* __restrict__ psi1){
    __shared__ float  xs[3600];
    __shared__ float2 xf[60*19];
    __shared__ float  ps1[480];
    int t = threadIdx.x;
    if (blockIdx.x < 128){
        int z = blockIdx.x;
        const float* xp = x + z*3600;
        for (int i = t; i < 3600; i += 256) xs[i] = xp[i];
        __syncthreads();
        for (int i = t; i < 1140; i += 256){
            int k = i/19, mi = i%19;
            float2 s = make_float2(0.f, 0.f);
            const float* row = &xs[k*60];
            for (int a = 0; a < 60; a++){
                float2 e = g_T60[mi*60 + a]; float v = row[a];
                s.x = fmaf(v, e.x, s.x); s.y = fmaf(v, e.y, s.y);
            }
            xf[i] = s;
        }
        __syncthreads();
        for (int i = t; i < 190; i += 256){
            int l = i/19, mi = i%19;
            float2 s = make_float2(0.f, 0.f);
            for (int k = 0; k < 60; k++){
                float w = g_wd_s2[(l*60 + k)*19 + mi];
                float2 v = xf[k*19 + mi];
                s.x = fmaf(w, v.x, s.x); s.y = fmaf(w, v.y, s.y);
            }
            g_X[(l*128 + z)*19 + mi] = s;
        }
    } else {
        int l = blockIdx.x - 128;   // 0..9
        for (int i = t; i < 480; i += 256) ps1[i] = psi1[i];
        __syncthreads();
        for (int i = t; i < 380; i += 256){
            int o = i/19, mi = i%19;
            float2 s = make_float2(0.f, 0.f);
            for (int g = 0; g < 24; g++){
                float w = ps1[o*24 + g];
                float2 y = g_Y1[(l*24 + g)*19 + mi];
                s.x = fmaf(w, y.x, s.x); s.y = fmaf(w, y.y, s.y);
            }
            g_Psi1[(l*20 + o)*19 + mi] = s;
        }
    }
}

// ---------------- launch 4 (kD): fused middle, Hermitian-halved ----------------
// Spectral domain kept only for m>=0 (S1-S3) and n>=0 (S4-S5); S6 reconstructs
// the full yf by conjugate mirroring (y real => all intermediates Hermitian).
#define CB 5
#define SMEM_D (8400*sizeof(float2))   // 67,200 B

__global__ __launch_bounds__(512, 1) void kD(){
    extern __shared__ float2 sm[];
    float2* XPh  = sm;             // [p][l][q][ni]: p*1900 + l*190 + q*19 + ni (q = m>=0)
    float2* sEi  = XPh + 3800;     // iE20 [mi*20+ang]
    float2* sEf  = sEi + 380;      // fE20 [fi*20+ang]
    float2* bufA = sEf + 220;      // per pair 1000 f2: Fh[bl*190+..] / Ytf(float)[bl*400+..] / yf[bl*66+..]
    float2* bufB = bufA + 2000;    // per pair 1000 f2: G[bl*200+..] / H[bl*120+..]
    float*  Ytf  = (float*)bufA;   // pair stride 2000 floats

    int z  = blockIdx.x/10;
    int c0 = (blockIdx.x%10)*2;
    int t  = threadIdx.x;

    for (int i = t; i < 380; i += 512) sEi[i] = g_iE20[i];
    for (int i = t; i < 220; i += 512) sEf[i] = g_fE20[i];
    for (int i = t; i < 3800; i += 512){
        int p = i/1900, rr = i%1900, l = rr/190, qn = rr%190, q = qn/19, ni = qn%19;
        XPh[i] = cmul(g_X[(l*128 + z)*19 + (9 + q)], g_Psi1[(l*20 + c0 + p)*19 + ni]);
    }
    float2 fx0 = make_float2(0.f,0.f), fx1 = make_float2(0.f,0.f), fx2 = make_float2(0.f,0.f);
    __syncthreads();

    for (int bc = 0; bc < 4; bc++){
        int b0 = bc*CB;
        // S1: Wigner synthesis, m>=0 only (380 items: 2 pairs x 10q x 19ni)
        if (t < 380){
            int p = t/190, rr = t%190, q = rr/19, ni = rr%19;
            int mn = (q + 9)*19 + ni;
            float2 a[CB];
            #pragma unroll
            for (int bl = 0; bl < CB; bl++) a[bl] = make_float2(0.f,0.f);
            #pragma unroll
            for (int l = 0; l < 10; l++){
                float2 v = XPh[p*1900 + l*190 + q*19 + ni];
                #pragma unroll
                for (int bl = 0; bl < CB; bl++){
                    float w = g_d1w[(l*20 + b0 + bl)*361 + mn];
                    a[bl].x = fmaf(w, v.x, a[bl].x);
                    a[bl].y = fmaf(w, v.y, a[bl].y);
                }
            }
            #pragma unroll
            for (int bl = 0; bl < CB; bl++) bufA[p*1000 + bl*190 + q*19 + ni] = a[bl];
        }
        __syncthreads();
        // S2: inverse DFT over n (full n range), rows m>=0, 2 g-cols/thread (200 threads)
        if (t < 200){
            int p = t/100, rr = t%100, q = rr/10, g0 = (rr%10)*2;
            float2 a[CB][2];
            #pragma unroll
            for (int bl = 0; bl < CB; bl++){ a[bl][0] = make_float2(0.f,0.f); a[bl][1] = make_float2(0.f,0.f); }
            #pragma unroll
            for (int ni = 0; ni < 19; ni++){
                float2 e0 = sEi[ni*20 + g0], e1 = sEi[ni*20 + g0 + 1];
                #pragma unroll
                for (int bl = 0; bl < CB; bl++){
                    float2 F = bufA[p*1000 + bl*190 + q*19 + ni];
                    cfma(a[bl][0], F, e0);
                    cfma(a[bl][1], F, e1);
                }
            }
            #pragma unroll
            for (int bl = 0; bl < CB; bl++){
                bufB[p*1000 + bl*200 + q*20 + g0]     = a[bl][0];
                bufB[p*1000 + bl*200 + q*20 + g0 + 1] = a[bl][1];
            }
        }
        __syncthreads();
        // S3: real inverse over m via half-spectrum (y = 2*sum_{q>=0}Re(G e) - G0.x) + relu
        if (t < 400){
            int p = t/200, rr = t%200, aa0 = (rr/20)*2, g = rr%20;
            float v[CB][2], q0x[CB];
            #pragma unroll
            for (int bl = 0; bl < CB; bl++){ v[bl][0] = 0.f; v[bl][1] = 0.f; }
            #pragma unroll
            for (int q = 0; q < 10; q++){
                float2 e0 = sEi[(q + 9)*20 + aa0], e1 = sEi[(q + 9)*20 + aa0 + 1];
                #pragma unroll
                for (int bl = 0; bl < CB; bl++){
                    float2 G = bufB[p*1000 + bl*200 + q*20 + g];
                    if (q == 0) q0x[bl] = G.x;
                    v[bl][0] = fmaf(G.x, e0.x, fmaf(-G.y, e0.y, v[bl][0]));
                    v[bl][1] = fmaf(G.x, e1.x, fmaf(-G.y, e1.y, v[bl][1]));
                }
            }
            #pragma unroll
            for (int bl = 0; bl < CB; bl++){
                Ytf[p*2000 + bl*400 + aa0*20 + g]     = fmaxf(2.f*v[bl][0] - q0x[bl], 0.f);
                Ytf[p*2000 + bl*400 + (aa0+1)*20 + g] = fmaxf(2.f*v[bl][1] - q0x[bl], 0.f);
            }
        }
        __syncthreads();
        // S4: forward DFT over g, n2 >= 0 only (240 threads: 2p x 20a x 6r)
        if (t < 240){
            int p = t/120, rr = t%120, aa = rr/6, r = rr%6;
            float2 s[CB];
            #pragma unroll
            for (int bl = 0; bl < CB; bl++) s[bl] = make_float2(0.f,0.f);
            #pragma unroll
            for (int g = 0; g < 20; g++){
                float2 e = sEf[(r + 5)*20 + g];
                #pragma unroll
                for (int bl = 0; bl < CB; bl++){
                    float y = Ytf[p*2000 + bl*400 + aa*20 + g];
                    s[bl].x = fmaf(y, e.x, s[bl].x);
                    s[bl].y = fmaf(y, e.y, s[bl].y);
                }
            }
            #pragma unroll
            for (int bl = 0; bl < CB; bl++) bufB[p*1000 + bl*120 + aa*6 + r] = s[bl];
        }
        __syncthreads();
        // S5: forward DFT over a, all m2, n2>=0 (132 threads: 2p x 11m x 6r)
        if (t < 132){
            int p = t/66, rr = t%66, m2 = rr/6, r = rr%6;
            float2 s[CB];
            #pragma unroll
            for (int bl = 0; bl < CB; bl++) s[bl] = make_float2(0.f,0.f);
            #pragma unroll
            for (int aa = 0; aa < 20; aa++){
                float2 e = sEf[m2*20 + aa];
                #pragma unroll
                for (int bl = 0; bl < CB; bl++){
                    float2 H = bufB[p*1000 + bl*120 + aa*6 + r];
                    cfma(s[bl], H, e);
                }
            }
            #pragma unroll
            for (int bl = 0; bl < CB; bl++) bufA[p*1000 + bl*66 + m2*6 + r] = s[bl];
        }
        __syncthreads();
        // S6: Wigner analysis over full mn, reconstructing yf by Hermitian mirror
        #pragma unroll
        for (int pass = 0; pass < 3; pass++){
            int j = t + pass*512;
            if (j < 1452){
                int p = j/726, rr = j%726, l = rr/121, mn = rr%121;
                int mi2 = mn/11, ni2 = mn%11;
                int srcm, srcr; float sy;
                if (ni2 >= 5){ srcm = mi2;      srcr = ni2 - 5; sy =  1.f; }
                else         { srcm = 10 - mi2; srcr = 5 - ni2; sy = -1.f; }
                float2* fx = (pass == 0) ? &fx0 : (pass == 1) ? &fx1 : &fx2;
                #pragma unroll
                for (int bl = 0; bl < CB; bl++){
                    float w = g_d12w[(l*20 + b0 + bl)*121 + mn];
                    float2 v = bufA[p*1000 + bl*66 + srcm*6 + srcr];
                    fx->x = fmaf(w, v.x, fx->x);
                    fx->y = fmaf(w*sy, v.y, fx->y);
                }
            }
        }
        __syncthreads();
    }
    {
        int j = t;
        int p = j/726, rr = j%726, l = rr/121, mn = rr%121;
        g_Fx[((l*128 + z)*20 + c0 + p)*121 + mn] = fx0;
    }
    {
        int j = t + 512;
        int p = j/726, rr = j%726, l = rr/121, mn = rr%121;
        g_Fx[((l*128 + z)*20 + c0 + p)*121 + mn] = fx1;
    }
    if (t + 1024 < 1452){
        int j = t + 1024;
        int p = j/726, rr = j%726, l = rr/121, mn = rr%121;
        g_Fx[((l*128 + z)*20 + c0 + p)*121 + mn] = fx2;
    }
}

// ---------------- launch 5 (kC): psi2 -> Psi2 dual form ----------------
__global__ void kC(const float* __restrict__ psi2){
    int l = blockIdx.x/20, i = blockIdx.x%20;
    __shared__ float ps[40*144];
    int t = threadIdx.x;
    for (int j = t; j < 5760; j += 128) ps[j] = psi2[i*5760 + j];
    __syncthreads();
    if (t >= 121) return;
    int mn = t;
    for (int oc = 0; oc < 40; oc += 8){
        float2 acc[8];
        #pragma unroll
        for (int u = 0; u < 8; u++) acc[u] = make_float2(0.f, 0.f);
        for (int g = 0; g < 144; g++){
            float2 d = g_D2[(l*144 + g)*121 + mn];
            #pragma unroll
            for (int u = 0; u < 8; u++){
                float w = ps[(oc+u)*144 + g];
                acc[u].x = fmaf(w, d.x, acc[u].x);
                acc[u].y = fmaf(w, d.y, acc[u].y);
            }
        }
        #pragma unroll
        for (int u = 0; u < 8; u++)
            g_Psi2d[((l*20 + i)*40 + (oc+u))*121 + mn] =
                make_float4(acc[u].x, acc[u].y, -acc[u].y, acc[u].x);
    }
}

// ---------------- launch 6 (kE): Fo (n>=0 half) = Fx * Psi2, f32x2 packed ----------------
__global__ __launch_bounds__(256) void kE(){
    int l  = blockIdx.x/64;
    int z0 = (blockIdx.x%64)*2;
    __shared__ float2 Fxs[4840];   // [zz][i][m][k]
    int t = threadIdx.x;
    for (int i = t; i < 4840; i += 256){
        int zz = i/2420, r = i%2420;
        Fxs[i] = g_Fx[(l*128 + z0 + zz)*2420 + r];
    }
    __syncthreads();
    if (t >= 240) return;
    int o = t/6, r = t%6;          // output col n = r (signed n>=0) -> Psi2 col r+5
    u64t acc[2][11];
    #pragma unroll
    for (int zz = 0; zz < 2; zz++)
        #pragma unroll
        for (int m = 0; m < 11; m++) acc[zz][m] = 0ULL;

    const ulonglong2* P = (const ulonglong2*)g_Psi2d;
    for (int i = 0; i < 20; i++){
        #pragma unroll
        for (int k = 0; k < 11; k++){
            ulonglong2 pA = P[((l*20 + i)*40 + o)*121 + k*11 + (r + 5)];
            #pragma unroll
            for (int m = 0; m < 11; m++){
                float2 f0 = Fxs[(i*11 + m)*11 + k];
                float2 f1 = Fxs[2420 + (i*11 + m)*11 + k];
                acc[0][m] = ffma2(pk2(f0.x, f0.x), pA.x, ffma2(pk2(f0.y, f0.y), pA.y, acc[0][m]));
                acc[1][m] = ffma2(pk2(f1.x, f1.x), pA.x, ffma2(pk2(f1.y, f1.y), pA.y, acc[1][m]));
            }
        }
    }
    #pragma unroll
    for (int zz = 0; zz < 2; zz++)
        #pragma unroll
        for (int m = 0; m < 11; m++)
            g_Foh[((l*128 + z0 + zz)*40 + o)*66 + m*6 + r] = upk(acc[zz][m]);
}

// ---------------- launch 7 (kF): half-spectrum synthesis + iDFT + relu + integrate ----------------
__global__ __launch_bounds__(144) void kF(){
    __shared__ float2 Fosh[396];      // [l][m2][r], r = n>=0
    __shared__ float2 Fh2s[12*66];    // [b][q][ni], q = m>=0
    __shared__ float2 G2s[12*72];     // [b][q][g]
    __shared__ float2 sE12[132];
    __shared__ float  red[144];
    int z = blockIdx.x/40, o = blockIdx.x%40;
    int t = threadIdx.x;
    if (t < 132) sE12[t] = g_iE12[t];
    for (int i = t; i < 396; i += 144){
        int l = i/66, rr = i%66;
        Fosh[i] = g_Foh[((l*128 + z)*40 + o)*66 + rr];
    }
    __syncthreads();
    // S1: Fh2[b][q][ni] (q = m>=0, all ni), reconstructing Fo via (-1)^{m+n} conj mirror
    if (t < 66){
        int q = t/11, ni = t%11;
        int mn = (q + 5)*11 + ni;
        float2 a[12];
        #pragma unroll
        for (int b = 0; b < 12; b++) a[b] = make_float2(0.f, 0.f);
        #pragma unroll
        for (int l = 0; l < 6; l++){
            float2 v;
            if (ni >= 5){
                v = Fosh[l*66 + (q + 5)*6 + (ni - 5)];
            } else {
                float2 vv = Fosh[l*66 + (5 - q)*6 + (5 - ni)];
                float s = ((q + 5 + ni) & 1) ? -1.f : 1.f;
                v = make_float2(s*vv.x, -s*vv.y);
            }
            #pragma unroll
            for (int b = 0; b < 12; b++){
                float w = g_d2w[(l*12 + b)*121 + mn];
                a[b].x = fmaf(w, v.x, a[b].x);
                a[b].y = fmaf(w, v.y, a[b].y);
            }
        }
        #pragma unroll
        for (int b = 0; b < 12; b++) Fh2s[b*66 + q*11 + ni] = a[b];
    }
    __syncthreads();
    // S2: inverse over n (full), rows m>=0 only (72 items)
    if (t < 72){
        int q = t/12, g = t%12;
        float2 a[12];
        #pragma unroll
        for (int b = 0; b < 12; b++) a[b] = make_float2(0.f, 0.f);
        #pragma unroll
        for (int ni = 0; ni < 11; ni++){
            float2 e = sE12[ni*12 + g];
            #pragma unroll
            for (int b = 0; b < 12; b++) cfma(a[b], Fh2s[b*66 + q*11 + ni], e);
        }
        #pragma unroll
        for (int b = 0; b < 12; b++) G2s[b*72 + q*12 + g] = a[b];
    }
    __syncthreads();
    // S3: real inverse over m via half-spectrum + relu + beta-weighted integrate
    float facc = 0.f;
    {
        int aa = t/12, g = t%12;
        float v[12], q0x[12];
        #pragma unroll
        for (int b = 0; b < 12; b++) v[b] = 0.f;
        #pragma unroll
        for (int q = 0; q < 6; q++){
            float2 e = sE12[(q + 5)*12 + aa];
            #pragma unroll
            for (int b = 0; b < 12; b++){
                float2 G = G2s[b*72 + q*12 + g];
                if (q == 0) q0x[b] = G.x;
                v[b] = fmaf(G.x, e.x, fmaf(-G.y, e.y, v[b]));
            }
        }
        #pragma unroll
        for (int b = 0; b < 12; b++)
            facc = fmaf(g_w2n[b], fmaxf(2.f*v[b] - q0x[b], 0.f), facc);
    }
    red[t] = facc;
    __syncthreads();
    if (t < 72) red[t] += red[t + 72];
    __syncthreads();
    if (t < 36) red[t] += red[t + 36];
    __syncthreads();
    if (t < 18) red[t] += red[t + 18];
    __syncthreads();
    if (t == 0){
        float s = 0.f;
        for (int i = 0; i < 18; i++) s += red[i];
        g_feat[z*40 + o] = s/144.f;
    }
}

// ---------------- launch 8 (kG): linear head ----------------
__global__ void kG(const float* __restrict__ wl, const float* __restrict__ bl,
                   float* __restrict__ out){
    int i = blockIdx.x*blockDim.x + threadIdx.x;
    if (i >= 1280) return;
    int z = i/10, f = i%10;
    float s = bl[f];
    for (int o = 0; o < 40; o++) s = fmaf(g_feat[z*40 + o], wl[f*40 + o], s);
    out[i] = s;
}

// ---------------- launch ----------------
extern "C" void kernel_launch(void* const* d_in, const int* in_sizes, int n_in,
                              void* d_out, int out_size){
    (void)in_sizes; (void)n_in; (void)out_size;
    const float* x    = (const float*)d_in[0];
    const float* psi1 = (const float*)d_in[1];
    const float* psi2 = (const float*)d_in[2];
    const float* wl   = (const float*)d_in[3];
    const float* bl   = (const float*)d_in[4];
    float* out = (float*)d_out;

    cudaFuncSetAttribute(kD, cudaFuncAttributeMaxDynamicSharedMemorySize, (int)SMEM_D);

    k_init_misc<<<1, 256>>>();                       // 1
    k_tabs<<<(N_TABS + 255)/256, 256>>>();           // 2
    kAB<<<138, 256>>>(x, psi1);                      // 3
    kD<<<1280, 512, SMEM_D>>>();                     // 4  <- ncu capture
    kC<<<120, 128>>>(psi2);                          // 5
    kE<<<384, 256>>>();                              // 6
    kF<<<5120, 144>>>();                             // 7
    kG<<<5, 256>>>(wl, bl, out);                     // 8
}

// round 8
// speedup vs baseline: 1.0001x; 1.0001x over previous
#include <cuda_runtime.h>
#include <math.h>

#define PI_D 3.14159265358979323846

typedef unsigned long long u64t;

// ---------------- complex / packed helpers ----------------
__device__ __forceinline__ float2 cmul(float2 a, float2 b){
    return make_float2(a.x*b.x - a.y*b.y, a.x*b.y + a.y*b.x);
}
__device__ __forceinline__ void cfma(float2 &acc, float2 a, float2 b){
    acc.x = fmaf(a.x, b.x, fmaf(-a.y, b.y, acc.x));
    acc.y = fmaf(a.x, b.y, fmaf( a.y, b.x, acc.y));
}
__device__ __forceinline__ u64t pk2(float lo, float hi){
    u64t r; asm("mov.b64 %0, {%1, %2};" : "=l"(r) : "f"(lo), "f"(hi)); return r;
}
__device__ __forceinline__ u64t ffma2(u64t a, u64t b, u64t c){
    u64t d; asm("fma.rn.f32x2 %0, %1, %2, %3;" : "=l"(d) : "l"(a), "l"(b), "l"(c)); return d;
}
__device__ __forceinline__ float2 upk(u64t v){
    float lo, hi; asm("mov.b64 {%0, %1}, %2;" : "=f"(lo), "=f"(hi) : "l"(v));
    return make_float2(lo, hi);
}

// ---------------- device-global scratch & constant tables ----------------
__device__ double g_lf[48];
__device__ double g_w30d[60];
__device__ double g_w10d[20];
__device__ double g_w6d[12];
__device__ float  g_w2n[12];

__device__ float2 g_T60[19*60];
__device__ float2 g_iE20[19*20];
__device__ float2 g_fE20[11*20];
__device__ float2 g_iE12[11*12];

__device__ float  g_wd_s2[10*60*19];
__device__ float2 g_Y1[10*24*19];
__device__ float  g_d1w[10*20*361];
__device__ float  g_d12w[6*20*121];
__device__ float2 g_D2[6*144*121];
__device__ float  g_d2w[6*12*121];

__device__ float2 g_X[10*128*19];
__device__ float2 g_Psi1[10*20*19];
__device__ float4 g_Psi2d[6*20*40*121];   // dual form (p.x, p.y, -p.y, p.x)
__device__ float2 g_Fx[6*128*20*121];
__device__ float2 g_Foh[6*128*40*66];     // Fo half-spectrum: n >= 0 (66 of 121)
__device__ float  g_feat[128*40];

// ---------------- Wigner-d (explicit formula, FP64) ----------------
__device__ double wdfun(int l, int m, int n, double beta){
    if (m > l || m < -l || n > l || n < -l) return 0.0;
    double cb = cos(0.5*beta), sb = sin(0.5*beta);
    double lcb = log(cb), lsb = log(sb);
    double pref = 0.5*(g_lf[l+m] + g_lf[l-m] + g_lf[l+n] + g_lf[l-n]);
    int s0 = max(0, n-m), s1 = min(l+n, l-m);
    double acc = 0.0;
    for (int s = s0; s <= s1; s++){
        double c = pref - (g_lf[l+n-s] + g_lf[s] + g_lf[m-n+s] + g_lf[l-m-s]);
        double e = exp(c + (double)(2*l + n - m - 2*s)*lcb + (double)(m - n + 2*s)*lsb);
        acc += ((m - n + s) & 1) ? -e : e;
    }
    return acc;
}

// ---------------- launch 1: init ----------------
__global__ void k_init_misc(){
    int t = threadIdx.x;
    if (t < 48) g_lf[t] = lgamma((double)t + 1.0);
    if (t < 60){
        double beta = PI_D*(2*t+1)/120.0; double s = 0;
        for (int j = 0; j < 30; j++) s += sin((2*j+1)*beta)/(2*j+1);
        g_w30d[t] = (2.0/30.0)*sin(beta)*s;
    }
    if (t < 20){
        double beta = PI_D*(2*t+1)/40.0; double s = 0;
        for (int j = 0; j < 10; j++) s += sin((2*j+1)*beta)/(2*j+1);
        g_w10d[t] = (2.0/10.0)*sin(beta)*s;
    }
    if (t < 12){
        double beta = PI_D*(2*t+1)/24.0; double s = 0;
        for (int j = 0; j < 6; j++) s += sin((2*j+1)*beta)/(2*j+1);
        g_w6d[t] = (2.0/6.0)*sin(beta)*s;
    }
    __syncthreads();
    if (t == 0){
        double s = 0;
        for (int i = 0; i < 12; i++) s += g_w6d[i];
        for (int i = 0; i < 12; i++) g_w2n[i] = (float)(g_w6d[i]/s);
    }
    for (int idx = t; idx < 19*60; idx += blockDim.x){
        int mi = idx/60, a = idx%60; int m = mi - 9;
        double sn, cs; sincospi(-(double)(m*a)/30.0, &sn, &cs);
        g_T60[idx] = make_float2((float)cs, (float)sn);
    }
    for (int idx = t; idx < 19*20; idx += blockDim.x){
        int mi = idx/20, a = idx%20; int m = mi - 9;
        double sn, cs; sincospi((double)(m*a)/10.0, &sn, &cs);
        g_iE20[idx] = make_float2((float)cs, (float)sn);
    }
    for (int idx = t; idx < 11*20; idx += blockDim.x){
        int mi = idx/20, a = idx%20; int m = mi - 5;
        double sn, cs; sincospi(-(double)(m*a)/10.0, &sn, &cs);
        g_fE20[idx] = make_float2((float)cs, (float)sn);
    }
    for (int idx = t; idx < 11*12; idx += blockDim.x){
        int mi = idx/12, a = idx%12; int m = mi - 5;
        double sn, cs; sincospi((double)(m*a)/6.0, &sn, &cs);
        g_iE12[idx] = make_float2((float)cs, (float)sn);
    }
}

// ---------------- launch 2: all Wigner tables ----------------
#define N_WDS2 (10*60*19)
#define N_Y1   (10*24*19)
#define N_D1W  (10*20*361)
#define N_D12W (6*20*121)
#define N_D2   (6*144*121)
#define N_D2W  (6*12*121)
#define N_TABS (N_WDS2+N_Y1+N_D1W+N_D12W+N_D2+N_D2W)

__global__ void k_tabs(){
    int idx = blockIdx.x*blockDim.x + threadIdx.x;
    if (idx < N_WDS2){
        int l = idx/(60*19); int r = idx%(60*19); int k = r/19; int mi = r%19;
        double beta = PI_D*(2*k+1)/120.0;
        g_wd_s2[idx] = (float)(g_w30d[k]*wdfun(l, mi-9, 0, beta));
        return;
    }
    idx -= N_WDS2;
    if (idx < N_Y1){
        int l = idx/456; int r = idx%456; int gp = r/19; int mi = r%19;
        int ib = gp/8, ia = gp%8; int m = mi - 9;
        double beta = (ib+1)*PI_D/24.0;
        double d = wdfun(l, m, 0, beta);
        double sn, cs; sincospi(-(double)(m*ia)/4.0, &sn, &cs);
        g_Y1[idx] = make_float2((float)(d*cs), (float)(d*sn));
        return;
    }
    idx -= N_Y1;
    if (idx < N_D1W){
        int l = idx/(20*361); int r = idx%(20*361); int b = r/361; int mn = r%361;
        int m = mn/19 - 9, n = mn%19 - 9;
        double beta = PI_D*(2*b+1)/40.0;
        g_d1w[idx] = (float)(wdfun(l, m, n, beta)*(double)(2*l+1));
        return;
    }
    idx -= N_D1W;
    if (idx < N_D12W){
        int l = idx/(20*121); int r = idx%(20*121); int b = r/121; int mn = r%121;
        int m = mn/11 - 5, n = mn%11 - 5;
        double beta = PI_D*(2*b+1)/40.0;
        g_d12w[idx] = (float)(wdfun(l, m, n, beta)*g_w10d[b]);
        return;
    }
    idx -= N_D12W;
    if (idx < N_D2){
        int l = idx/(144*121); int r = idx%(144*121); int gp = r/121; int mn = r%121;
        int m = mn/11 - 5, n = mn%11 - 5;
        int ib = gp/48, ia = (gp/6)%8, ig = gp%6;
        double beta = (ib+1)*PI_D/24.0;
        double d = wdfun(l, m, n, beta);
        double ph = -((double)(m*ia)/4.0 + (double)(n*ig)/3.0);
        double sn, cs; sincospi(ph, &sn, &cs);
        g_D2[idx] = make_float2((float)(d*cs), (float)(d*sn));
        return;
    }
    idx -= N_D2;
    if (idx < N_D2W){
        int l = idx/(12*121); int r = idx%(12*121); int b = r/121; int mn = r%121;
        int m = mn/11 - 5, n = mn%11 - 5;
        double beta = PI_D*(2*b+1)/24.0;
        g_d2w[idx] = (float)(wdfun(l, m, n, beta)*(double)(2*l+1));
        return;
    }
}

// ---------------- launch 3 (kAB): kA (blocks 0-127) + kB (blocks 128-137) ----------------
__global__ void kAB(const float* __restrict__ x, const float* __restrict__ psi1){
    __shared__ float  xs[3600];
    __shared__ float2 xf[60*19];
    __shared__ float  ps1[480];
    int t = threadIdx.x;
    if (blockIdx.x < 128){
        int z = blockIdx.x;
        const float* xp = x + z*3600;
        for (int i = t; i < 3600; i += 256) xs[i] = xp[i];
        __syncthreads();
        for (int i = t; i < 1140; i += 256){
            int k = i/19, mi = i%19;
            float2 s = make_float2(0.f, 0.f);
            const float* row = &xs[k*60];
            for (int a = 0; a < 60; a++){
                float2 e = g_T60[mi*60 + a]; float v = row[a];
                s.x = fmaf(v, e.x, s.x); s.y = fmaf(v, e.y, s.y);
            }
            xf[i] = s;
        }
        __syncthreads();
        for (int i = t; i < 190; i += 256){
            int l = i/19, mi = i%19;
            float2 s = make_float2(0.f, 0.f);
            for (int k = 0; k < 60; k++){
                float w = g_wd_s2[(l*60 + k)*19 + mi];
                float2 v = xf[k*19 + mi];
                s.x = fmaf(w, v.x, s.x); s.y = fmaf(w, v.y, s.y);
            }
            g_X[(l*128 + z)*19 + mi] = s;
        }
    } else {
        int l = blockIdx.x - 128;   // 0..9
        for (int i = t; i < 480; i += 256) ps1[i] = psi1[i];
        __syncthreads();
        for (int i = t; i < 380; i += 256){
            int o = i/19, mi = i%19;
            float2 s = make_float2(0.f, 0.f);
            for (int g = 0; g < 24; g++){
                float w = ps1[o*24 + g];
                float2 y = g_Y1[(l*24 + g)*19 + mi];
                s.x = fmaf(w, y.x, s.x); s.y = fmaf(w, y.y, s.y);
            }
            g_Psi1[(l*20 + o)*19 + mi] = s;
        }
    }
}

// ---------------- launch 4 (kD): fused middle, Hermitian-halved ----------------
// Spectral domain kept only for m>=0 (S1-S3) and n>=0 (S4-S5); S6 reconstructs
// the full yf by conjugate mirroring (y real => all intermediates Hermitian).
#define CB 5
#define SMEM_D (8400*sizeof(float2))   // 67,200 B

__global__ __launch_bounds__(512, 1) void kD(){
    extern __shared__ float2 sm[];
    float2* XPh  = sm;             // [p][l][q][ni]: p*1900 + l*190 + q*19 + ni (q = m>=0)
    float2* sEi  = XPh + 3800;     // iE20 [mi*20+ang]
    float2* sEf  = sEi + 380;      // fE20 [fi*20+ang]
    float2* bufA = sEf + 220;      // per pair 1000 f2: Fh[bl*190+..] / Ytf(float)[bl*400+..] / yf[bl*66+..]
    float2* bufB = bufA + 2000;    // per pair 1000 f2: G[bl*200+..] / H[bl*120+..]
    float*  Ytf  = (float*)bufA;   // pair stride 2000 floats

    int z  = blockIdx.x/10;
    int c0 = (blockIdx.x%10)*2;
    int t  = threadIdx.x;

    for (int i = t; i < 380; i += 512) sEi[i] = g_iE20[i];
    for (int i = t; i < 220; i += 512) sEf[i] = g_fE20[i];
    for (int i = t; i < 3800; i += 512){
        int p = i/1900, rr = i%1900, l = rr/190, qn = rr%190, q = qn/19, ni = qn%19;
        XPh[i] = cmul(g_X[(l*128 + z)*19 + (9 + q)], g_Psi1[(l*20 + c0 + p)*19 + ni]);
    }
    float2 fx0 = make_float2(0.f,0.f), fx1 = make_float2(0.f,0.f), fx2 = make_float2(0.f,0.f);
    __syncthreads();

    for (int bc = 0; bc < 4; bc++){
        int b0 = bc*CB;
        // S1: Wigner synthesis, m>=0 only (380 items: 2 pairs x 10q x 19ni)
        if (t < 380){
            int p = t/190, rr = t%190, q = rr/19, ni = rr%19;
            int mn = (q + 9)*19 + ni;
            float2 a[CB];
            #pragma unroll
            for (int bl = 0; bl < CB; bl++) a[bl] = make_float2(0.f,0.f);
            #pragma unroll
            for (int l = 0; l < 10; l++){
                float2 v = XPh[p*1900 + l*190 + q*19 + ni];
                #pragma unroll
                for (int bl = 0; bl < CB; bl++){
                    float w = g_d1w[(l*20 + b0 + bl)*361 + mn];
                    a[bl].x = fmaf(w, v.x, a[bl].x);
                    a[bl].y = fmaf(w, v.y, a[bl].y);
                }
            }
            #pragma unroll
            for (int bl = 0; bl < CB; bl++) bufA[p*1000 + bl*190 + q*19 + ni] = a[bl];
        }
        __syncthreads();
        // S2: inverse DFT over n (full n range), rows m>=0, 2 g-cols/thread (200 threads)
        if (t < 200){
            int p = t/100, rr = t%100, q = rr/10, g0 = (rr%10)*2;
            float2 a[CB][2];
            #pragma unroll
            for (int bl = 0; bl < CB; bl++){ a[bl][0] = make_float2(0.f,0.f); a[bl][1] = make_float2(0.f,0.f); }
            #pragma unroll
            for (int ni = 0; ni < 19; ni++){
                float2 e0 = sEi[ni*20 + g0], e1 = sEi[ni*20 + g0 + 1];
                #pragma unroll
                for (int bl = 0; bl < CB; bl++){
                    float2 F = bufA[p*1000 + bl*190 + q*19 + ni];
                    cfma(a[bl][0], F, e0);
                    cfma(a[bl][1], F, e1);
                }
            }
            #pragma unroll
            for (int bl = 0; bl < CB; bl++){
                bufB[p*1000 + bl*200 + q*20 + g0]     = a[bl][0];
                bufB[p*1000 + bl*200 + q*20 + g0 + 1] = a[bl][1];
            }
        }
        __syncthreads();
        // S3: real inverse over m via half-spectrum (y = 2*sum_{q>=0}Re(G e) - G0.x) + relu
        if (t < 400){
            int p = t/200, rr = t%200, aa0 = (rr/20)*2, g = rr%20;
            float v[CB][2], q0x[CB];
            #pragma unroll
            for (int bl = 0; bl < CB; bl++){ v[bl][0] = 0.f; v[bl][1] = 0.f; }
            #pragma unroll
            for (int q = 0; q < 10; q++){
                float2 e0 = sEi[(q + 9)*20 + aa0], e1 = sEi[(q + 9)*20 + aa0 + 1];
                #pragma unroll
                for (int bl = 0; bl < CB; bl++){
                    float2 G = bufB[p*1000 + bl*200 + q*20 + g];
                    if (q == 0) q0x[bl] = G.x;
                    v[bl][0] = fmaf(G.x, e0.x, fmaf(-G.y, e0.y, v[bl][0]));
                    v[bl][1] = fmaf(G.x, e1.x, fmaf(-G.y, e1.y, v[bl][1]));
                }
            }
            #pragma unroll
            for (int bl = 0; bl < CB; bl++){
                Ytf[p*2000 + bl*400 + aa0*20 + g]     = fmaxf(2.f*v[bl][0] - q0x[bl], 0.f);
                Ytf[p*2000 + bl*400 + (aa0+1)*20 + g] = fmaxf(2.f*v[bl][1] - q0x[bl], 0.f);
            }
        }
        __syncthreads();
        // S4: forward DFT over g, n2 >= 0 only (240 threads: 2p x 20a x 6r)
        if (t < 240){
            int p = t/120, rr = t%120, aa = rr/6, r = rr%6;
            float2 s[CB];
            #pragma unroll
            for (int bl = 0; bl < CB; bl++) s[bl] = make_float2(0.f,0.f);
            #pragma unroll
            for (int g = 0; g < 20; g++){
                float2 e = sEf[(r + 5)*20 + g];
                #pragma unroll
                for (int bl = 0; bl < CB; bl++){
                    float y = Ytf[p*2000 + bl*400 + aa*20 + g];
                    s[bl].x = fmaf(y, e.x, s[bl].x);
                    s[bl].y = fmaf(y, e.y, s[bl].y);
                }
            }
            #pragma unroll
            for (int bl = 0; bl < CB; bl++) bufB[p*1000 + bl*120 + aa*6 + r] = s[bl];
        }
        __syncthreads();
        // S5: forward DFT over a, all m2, n2>=0 (132 threads: 2p x 11m x 6r)
        if (t < 132){
            int p = t/66, rr = t%66, m2 = rr/6, r = rr%6;
            float2 s[CB];
            #pragma unroll
            for (int bl = 0; bl < CB; bl++) s[bl] = make_float2(0.f,0.f);
            #pragma unroll
            for (int aa = 0; aa < 20; aa++){
                float2 e = sEf[m2*20 + aa];
                #pragma unroll
                for (int bl = 0; bl < CB; bl++){
                    float2 H = bufB[p*1000 + bl*120 + aa*6 + r];
                    cfma(s[bl], H, e);
                }
            }
            #pragma unroll
            for (int bl = 0; bl < CB; bl++) bufA[p*1000 + bl*66 + m2*6 + r] = s[bl];
        }
        __syncthreads();
        // S6: Wigner analysis over full mn, reconstructing yf by Hermitian mirror
        #pragma unroll
        for (int pass = 0; pass < 3; pass++){
            int j = t + pass*512;
            if (j < 1452){
                int p = j/726, rr = j%726, l = rr/121, mn = rr%121;
                int mi2 = mn/11, ni2 = mn%11;
                int srcm, srcr; float sy;
                if (ni2 >= 5){ srcm = mi2;      srcr = ni2 - 5; sy =  1.f; }
                else         { srcm = 10 - mi2; srcr = 5 - ni2; sy = -1.f; }
                float2* fx = (pass == 0) ? &fx0 : (pass == 1) ? &fx1 : &fx2;
                #pragma unroll
                for (int bl = 0; bl < CB; bl++){
                    float w = g_d12w[(l*20 + b0 + bl)*121 + mn];
                    float2 v = bufA[p*1000 + bl*66 + srcm*6 + srcr];
                    fx->x = fmaf(w, v.x, fx->x);
                    fx->y = fmaf(w*sy, v.y, fx->y);
                }
            }
        }
        __syncthreads();
    }
    {
        int j = t;
        int p = j/726, rr = j%726, l = rr/121, mn = rr%121;
        g_Fx[((l*128 + z)*20 + c0 + p)*121 + mn] = fx0;
    }
    {
        int j = t + 512;
        int p = j/726, rr = j%726, l = rr/121, mn = rr%121;
        g_Fx[((l*128 + z)*20 + c0 + p)*121 + mn] = fx1;
    }
    if (t + 1024 < 1452){
        int j = t + 1024;
        int p = j/726, rr = j%726, l = rr/121, mn = rr%121;
        g_Fx[((l*128 + z)*20 + c0 + p)*121 + mn] = fx2;
    }
}

// ---------------- launch 5 (kC): psi2 -> Psi2 dual form ----------------
__global__ void kC(const float* __restrict__ psi2){
    int l = blockIdx.x/20, i = blockIdx.x%20;
    __shared__ float ps[40*144];
    int t = threadIdx.x;
    for (int j = t; j < 5760; j += 128) ps[j] = psi2[i*5760 + j];
    __syncthreads();
    if (t >= 121) return;
    int mn = t;
    for (int oc = 0; oc < 40; oc += 8){
        float2 acc[8];
        #pragma unroll
        for (int u = 0; u < 8; u++) acc[u] = make_float2(0.f, 0.f);
        for (int g = 0; g < 144; g++){
            float2 d = g_D2[(l*144 + g)*121 + mn];
            #pragma unroll
            for (int u = 0; u < 8; u++){
                float w = ps[(oc+u)*144 + g];
                acc[u].x = fmaf(w, d.x, acc[u].x);
                acc[u].y = fmaf(w, d.y, acc[u].y);
            }
        }
        #pragma unroll
        for (int u = 0; u < 8; u++)
            g_Psi2d[((l*20 + i)*40 + (oc+u))*121 + mn] =
                make_float4(acc[u].x, acc[u].y, -acc[u].y, acc[u].x);
    }
}

// ---------------- launch 6 (kE): Fo (n>=0 half) = Fx * Psi2, f32x2 packed ----------------
__global__ __launch_bounds__(256) void kE(){
    int l  = blockIdx.x/64;
    int z0 = (blockIdx.x%64)*2;
    __shared__ float2 Fxs[4840];   // [zz][i][m][k]
    int t = threadIdx.x;
    for (int i = t; i < 4840; i += 256){
        int zz = i/2420, r = i%2420;
        Fxs[i] = g_Fx[(l*128 + z0 + zz)*2420 + r];
    }
    __syncthreads();
    if (t >= 240) return;
    int o = t/6, r = t%6;          // output col n = r (signed n>=0) -> Psi2 col r+5
    u64t acc[2][11];
    #pragma unroll
    for (int zz = 0; zz < 2; zz++)
        #pragma unroll
        for (int m = 0; m < 11; m++) acc[zz][m] = 0ULL;

    const ulonglong2* P = (const ulonglong2*)g_Psi2d;
    for (int i = 0; i < 20; i++){
        #pragma unroll
        for (int k = 0; k < 11; k++){
            ulonglong2 pA = P[((l*20 + i)*40 + o)*121 + k*11 + (r + 5)];
            #pragma unroll
            for (int m = 0; m < 11; m++){
                float2 f0 = Fxs[(i*11 + m)*11 + k];
                float2 f1 = Fxs[2420 + (i*11 + m)*11 + k];
                acc[0][m] = ffma2(pk2(f0.x, f0.x), pA.x, ffma2(pk2(f0.y, f0.y), pA.y, acc[0][m]));
                acc[1][m] = ffma2(pk2(f1.x, f1.x), pA.x, ffma2(pk2(f1.y, f1.y), pA.y, acc[1][m]));
            }
        }
    }
    #pragma unroll
    for (int zz = 0; zz < 2; zz++)
        #pragma unroll
        for (int m = 0; m < 11; m++)
            g_Foh[((l*128 + z0 + zz)*40 + o)*66 + m*6 + r] = upk(acc[zz][m]);
}

// ---------------- launch 7 (kF): half-spectrum synthesis + iDFT + relu + integrate ----------------
__global__ __launch_bounds__(144) void kF(){
    __shared__ float2 Fosh[396];      // [l][m2][r], r = n>=0
    __shared__ float2 Fh2s[12*66];    // [b][q][ni], q = m>=0
    __shared__ float2 G2s[12*72];     // [b][q][g]
    __shared__ float2 sE12[132];
    __shared__ float  red[144];
    int z = blockIdx.x/40, o = blockIdx.x%40;
    int t = threadIdx.x;
    if (t < 132) sE12[t] = g_iE12[t];
    for (int i = t; i < 396; i += 144){
        int l = i/66, rr = i%66;
        Fosh[i] = g_Foh[((l*128 + z)*40 + o)*66 + rr];
    }
    __syncthreads();
    // S1: Fh2[b][q][ni] (q = m>=0, all ni), reconstructing Fo via (-1)^{m+n} conj mirror
    if (t < 66){
        int q = t/11, ni = t%11;
        int mn = (q + 5)*11 + ni;
        float2 a[12];
        #pragma unroll
        for (int b = 0; b < 12; b++) a[b] = make_float2(0.f, 0.f);
        #pragma unroll
        for (int l = 0; l < 6; l++){
            float2 v;
            if (ni >= 5){
                v = Fosh[l*66 + (q + 5)*6 + (ni - 5)];
            } else {
                float2 vv = Fosh[l*66 + (5 - q)*6 + (5 - ni)];
                float s = ((q + 5 + ni) & 1) ? -1.f : 1.f;
                v = make_float2(s*vv.x, -s*vv.y);
            }
            #pragma unroll
            for (int b = 0; b < 12; b++){
                float w = g_d2w[(l*12 + b)*121 + mn];
                a[b].x = fmaf(w, v.x, a[b].x);
                a[b].y = fmaf(w, v.y, a[b].y);
            }
        }
        #pragma unroll
        for (int b = 0; b < 12; b++) Fh2s[b*66 + q*11 + ni] = a[b];
    }
    __syncthreads();
    // S2: inverse over n (full), rows m>=0 only (72 items)
    if (t < 72){
        int q = t/12, g = t%12;
        float2 a[12];
        #pragma unroll
        for (int b = 0; b < 12; b++) a[b] = make_float2(0.f, 0.f);
        #pragma unroll
        for (int ni = 0; ni < 11; ni++){
            float2 e = sE12[ni*12 + g];
            #pragma unroll
            for (int b = 0; b < 12; b++) cfma(a[b], Fh2s[b*66 + q*11 + ni], e);
        }
        #pragma unroll
        for (int b = 0; b < 12; b++) G2s[b*72 + q*12 + g] = a[b];
    }
    __syncthreads();
    // S3: real inverse over m via half-spectrum + relu + beta-weighted integrate
    float facc = 0.f;
    {
        int aa = t/12, g = t%12;
        float v[12], q0x[12];
        #pragma unroll
        for (int b = 0; b < 12; b++) v[b] = 0.f;
        #pragma unroll
        for (int q = 0; q < 6; q++){
            float2 e = sE12[(q + 5)*12 + aa];
            #pragma unroll
            for (int b = 0; b < 12; b++){
                float2 G = G2s[b*72 + q*12 + g];
                if (q == 0) q0x[b] = G.x;
                v[b] = fmaf(G.x, e.x, fmaf(-G.y, e.y, v[b]));
            }
        }
        #pragma unroll
        for (int b = 0; b < 12; b++)
            facc = fmaf(g_w2n[b], fmaxf(2.f*v[b] - q0x[b], 0.f), facc);
    }
    red[t] = facc;
    __syncthreads();
    if (t < 72) red[t] += red[t + 72];
    __syncthreads();
    if (t < 36) red[t] += red[t + 36];
    __syncthreads();
    if (t < 18) red[t] += red[t + 18];
    __syncthreads();
    if (t == 0){
        float s = 0.f;
        for (int i = 0; i < 18; i++) s += red[i];
        g_feat[z*40 + o] = s/144.f;
    }
}

// ---------------- launch 8 (kG): linear head ----------------
__global__ void kG(const float* __restrict__ wl, const float* __restrict__ bl,
                   float* __restrict__ out){
    int i = blockIdx.x*blockDim.x + threadIdx.x;
    if (i >= 1280) return;
    int z = i/10, f = i%10;
    float s = bl[f];
    for (int o = 0; o < 40; o++) s = fmaf(g_feat[z*40 + o], wl[f*40 + o], s);
    out[i] = s;
}

// ---------------- launch ----------------
extern "C" void kernel_launch(void* const* d_in, const int* in_sizes, int n_in,
                              void* d_out, int out_size){
    (void)in_sizes; (void)n_in; (void)out_size;
    const float* x    = (const float*)d_in[0];
    const float* psi1 = (const float*)d_in[1];
    const float* psi2 = (const float*)d_in[2];
    const float* wl   = (const float*)d_in[3];
    const float* bl   = (const float*)d_in[4];
    float* out = (float*)d_out;

    cudaFuncSetAttribute(kD, cudaFuncAttributeMaxDynamicSharedMemorySize, (int)SMEM_D);

    k_init_misc<<<1, 256>>>();                       // 1
    k_tabs<<<(N_TABS + 255)/256, 256>>>();           // 2
    kAB<<<138, 256>>>(x, psi1);                      // 3
    kD<<<1280, 512, SMEM_D>>>();                     // 4  <- ncu capture
    kC<<<120, 128>>>(psi2);                          // 5
    kE<<<384, 256>>>();                              // 6
    kF<<<5120, 144>>>();                             // 7
    kG<<<5, 256>>>(wl, bl, out);                     // 8
}